// round 7
// baseline (speedup 1.0000x reference)
#include <cuda_runtime.h>
#include <cstddef>

// Problem constants (fixed by the dataset instance)
#define MM   4
#define AA   256
#define RBF  64
#define FF   32
#define HH   32
#define SI   32
#define CC   128   // 4 filters * FF radial columns

// Precombined radial weights, row-major over k: g_Wt[k*CC + c]
__device__ float g_Wt[RBF * CC];
__device__ float g_bias[CC];

struct Wptrs {
    const float* w1[4];
    const float* b1[4];
    const float* w2[4];
    const float* b2[4];
};

// ---------------------------------------------------------------------------
// Precompute W = w1 @ w2 (per filter), bias = b1 @ w2 + b2.
// g_Wt[k][c], c = filt*32 + f  (filt order: 00, 01, 10, 11).
// ---------------------------------------------------------------------------
__global__ void prep_kernel(Wptrs wp) {
    int idx = blockIdx.x * blockDim.x + threadIdx.x;
    if (idx < CC * RBF) {
        int c = idx & (CC - 1);
        int k = idx >> 7;
        int filt = c >> 5;
        int f = c & 31;
        const float* w1 = wp.w1[filt];
        const float* w2 = wp.w2[filt];
        float s = 0.f;
#pragma unroll
        for (int h = 0; h < HH; h++)
            s += w1[k * HH + h] * w2[h * FF + f];
        g_Wt[k * CC + c] = s;
        if (k == 0) {
            float bs = wp.b2[filt][f];
            const float* b1 = wp.b1[filt];
#pragma unroll
            for (int h = 0; h < HH; h++)
                bs += b1[h] * w2[h * FF + f];
            g_bias[c] = bs;
        }
    }
}

// ---------------------------------------------------------------------------
// Packed fp32x2 helpers (Blackwell FFMA2 — PTX-only path)
// ---------------------------------------------------------------------------
typedef unsigned long long u64;

__device__ __forceinline__ u64 ffma2(u64 a, u64 b, u64 c) {
    u64 d;
    asm("fma.rn.f32x2 %0, %1, %2, %3;" : "=l"(d) : "l"(a), "l"(b), "l"(c));
    return d;
}
__device__ __forceinline__ u64 splat2(float x) {
    u64 d;
    asm("mov.b64 %0, {%1, %1};" : "=l"(d) : "f"(x));
    return d;
}
__device__ __forceinline__ float2 unpk(u64 a) {
    float2 r;
    asm("mov.b64 {%0, %1}, %2;" : "=f"(r.x), "=f"(r.y) : "l"(a));
    return r;
}
__device__ __forceinline__ float sspf(float x) {
    return logf(0.5f * expf(x) + 0.5f);   // shifted softplus
}

// ---------------------------------------------------------------------------
// Main fused kernel: one block per (m, a).  256 threads.
//   tc = tid>>3 (0..31): 4 radial columns c = 4*tc..4*tc+3 (one filter/warp)
//   tb = tid&7  (0..7) : 8 neighbor rows per 64-row chunk
// Radial GEMM is register-tiled 8b x 4c with packed f32x2 accumulators;
// image chunk lives transposed in smem (Ism[k][b]); W streamed via LDG.128.
// ---------------------------------------------------------------------------
__global__ void __launch_bounds__(256, 2) conv_kernel(
    const float* __restrict__ image,
    const float* __restrict__ vectors,
    const float* __restrict__ feat0,
    const float* __restrict__ feat1,
    const float* __restrict__ w_si0,
    const float* __restrict__ w_si1,
    const float* __restrict__ b_act0,
    const float* __restrict__ b_act1,
    float* __restrict__ out)
{
    const int ma  = blockIdx.x;        // m*AA + a
    const int m   = ma >> 8;
    const int tid = threadIdx.x;
    const int tc  = tid >> 3;          // 0..31 column group
    const int tb  = tid & 7;           // 0..7  b group
    const int filt  = tc >> 3;         // 0..3 (uniform within warp)
    const int fbase = (tc & 7) * 4;    // f of ci=0

    __shared__ __align__(16) float s_buf[RBF * 64];  // Ism[k][b]; later s_red
    __shared__ float s_v[64][4];
    __shared__ float s_cat[FF][12];

    float (*Ism)[64] = (float (*)[64])s_buf;

    const float* imgbase = image   + (size_t)ma * (AA * RBF);
    const float* vbase   = vectors + (size_t)ma * (AA * 3);
    const float* f0base  = feat0   + (size_t)m  * (AA * FF);
    const float* f1base  = feat1   + (size_t)m  * (AA * FF * 3);

    float bias[4];
    {
        float4 bb = *(const float4*)(g_bias + tc * 4);
        bias[0] = bb.x; bias[1] = bb.y; bias[2] = bb.z; bias[3] = bb.w;
    }

    float acc[4][4];
#pragma unroll
    for (int ci = 0; ci < 4; ci++)
#pragma unroll
        for (int sl = 0; sl < 4; sl++) acc[ci][sl] = 0.f;

    // ---- register-staged image/vector chunk staging ----
    const int sb  = tid & 63;          // b row within chunk
    const int skq = tid >> 6;          // which 16-k slice
    float4 sI[4];
    float  sv = 0.f;

    auto loadregs = [&](int chunk) {
        const float4* src = (const float4*)(imgbase +
            (size_t)(chunk * 64 + sb) * RBF + skq * 16);
#pragma unroll
        for (int j = 0; j < 4; j++) sI[j] = src[j];
        if (tid < 192) sv = vbase[chunk * 192 + tid];
    };
    auto stsregs = [&]() {
#pragma unroll
        for (int j = 0; j < 4; j++) {
            const int k0 = skq * 16 + j * 4;
            Ism[k0 + 0][sb] = sI[j].x;
            Ism[k0 + 1][sb] = sI[j].y;
            Ism[k0 + 2][sb] = sI[j].z;
            Ism[k0 + 3][sb] = sI[j].w;
        }
        if (tid < 192) s_v[tid / 3][tid % 3] = sv;
    };

    loadregs(0);
    stsregs();
    __syncthreads();

    const float* wbase = g_Wt + tc * 4;

    for (int chunk = 0; chunk < 4; chunk++) {
        if (chunk < 3) loadregs(chunk + 1);   // prefetch next chunk into regs

        // ---- 8b x 4c register-tiled GEMM over k=64 ----
        u64 t[4][4];
#pragma unroll
        for (int ci = 0; ci < 4; ci++)
#pragma unroll
            for (int bp = 0; bp < 4; bp++) t[ci][bp] = 0ULL;

#pragma unroll 8
        for (int k = 0; k < 64; k++) {
            float4 w4 = *(const float4*)(wbase + k * CC);       // LDG.128 (L1)
            const u64* ip = (const u64*)&Ism[k][tb * 8];        // 2x LDS.128
            u64 i0 = ip[0], i1 = ip[1], i2 = ip[2], i3 = ip[3];
            u64 w0 = splat2(w4.x), w1 = splat2(w4.y);
            u64 w2 = splat2(w4.z), w3 = splat2(w4.w);
            t[0][0] = ffma2(i0, w0, t[0][0]); t[0][1] = ffma2(i1, w0, t[0][1]);
            t[0][2] = ffma2(i2, w0, t[0][2]); t[0][3] = ffma2(i3, w0, t[0][3]);
            t[1][0] = ffma2(i0, w1, t[1][0]); t[1][1] = ffma2(i1, w1, t[1][1]);
            t[1][2] = ffma2(i2, w1, t[1][2]); t[1][3] = ffma2(i3, w1, t[1][3]);
            t[2][0] = ffma2(i0, w2, t[2][0]); t[2][1] = ffma2(i1, w2, t[2][1]);
            t[2][2] = ffma2(i2, w2, t[2][2]); t[2][3] = ffma2(i3, w2, t[2][3]);
            t[3][0] = ffma2(i0, w3, t[3][0]); t[3][1] = ffma2(i1, w3, t[3][1]);
            t[3][2] = ffma2(i2, w3, t[3][2]); t[3][3] = ffma2(i3, w3, t[3][3]);
        }

        // ---- immediate contraction over this chunk's 8 b rows ----
#pragma unroll
        for (int bp = 0; bp < 4; bp++) {
            float r[2][4];
#pragma unroll
            for (int ci = 0; ci < 4; ci++) {
                float2 u = unpk(t[ci][bp]);
                r[0][ci] = u.x + bias[ci];
                r[1][ci] = u.y + bias[ci];
            }
#pragma unroll
            for (int h = 0; h < 2; h++) {
                const int bl = tb * 8 + bp * 2 + h;
                const int b  = chunk * 64 + bl;

                if (filt == 0) {
                    // out_0x0_0: acc0 += r * feat0
                    float4 p = *(const float4*)(f0base + b * FF + fbase);
                    acc[0][0] += r[h][0] * p.x;
                    acc[1][0] += r[h][1] * p.y;
                    acc[2][0] += r[h][2] * p.z;
                    acc[3][0] += r[h][3] * p.w;
                } else if (filt == 1) {
                    // out_0x1_1: acc[0..2] += (r*mask)*feat0 * v
                    float vx = s_v[bl][0], vy = s_v[bl][1], vz = s_v[bl][2];
                    float n2 = vx * vx + vy * vy + vz * vz;
                    float mk = (n2 < 1e-14f) ? 0.f : 1.f;
                    float4 p = *(const float4*)(f0base + b * FF + fbase);
                    float pp[4] = {p.x, p.y, p.z, p.w};
#pragma unroll
                    for (int ci = 0; ci < 4; ci++) {
                        float tp = r[h][ci] * mk * pp[ci];
                        acc[ci][0] += tp * vx;
                        acc[ci][1] += tp * vy;
                        acc[ci][2] += tp * vz;
                    }
                } else if (filt == 2) {
                    // out_1x0_1: acc[0..2] += r * feat1
                    const float4* qp = (const float4*)(f1base +
                        (size_t)(b * FF + fbase) * 3);
                    float4 qa = qp[0], qb = qp[1], qc = qp[2];
                    float q[12] = {qa.x, qa.y, qa.z, qa.w,
                                   qb.x, qb.y, qb.z, qb.w,
                                   qc.x, qc.y, qc.z, qc.w};
#pragma unroll
                    for (int ci = 0; ci < 4; ci++) {
                        acc[ci][0] += r[h][ci] * q[ci * 3 + 0];
                        acc[ci][1] += r[h][ci] * q[ci * 3 + 1];
                        acc[ci][2] += r[h][ci] * q[ci * 3 + 2];
                    }
                } else {
                    // out_1x1_0 (v.q) + out_1x1_1 (v x q)
                    float vx = s_v[bl][0], vy = s_v[bl][1], vz = s_v[bl][2];
                    float n2 = vx * vx + vy * vy + vz * vz;
                    float mk = (n2 < 1e-14f) ? 0.f : 1.f;
                    const float4* qp = (const float4*)(f1base +
                        (size_t)(b * FF + fbase) * 3);
                    float4 qa = qp[0], qb = qp[1], qc = qp[2];
                    float q[12] = {qa.x, qa.y, qa.z, qa.w,
                                   qb.x, qb.y, qb.z, qb.w,
                                   qc.x, qc.y, qc.z, qc.w};
#pragma unroll
                    for (int ci = 0; ci < 4; ci++) {
                        float rm = r[h][ci] * mk;
                        float q0 = q[ci * 3], q1 = q[ci * 3 + 1], q2 = q[ci * 3 + 2];
                        acc[ci][0] += rm * (vx * q0 + vy * q1 + vz * q2);
                        acc[ci][1] += rm * (vy * q2 - vz * q1);
                        acc[ci][2] += rm * (vz * q0 - vx * q2);
                        acc[ci][3] += rm * (vx * q1 - vy * q0);
                    }
                }
            }
        }

        __syncthreads();                 // everyone done reading Ism / s_v
        if (chunk < 3) {
            stsregs();                   // write next chunk
            __syncthreads();
        }
    }

    // ---- reduce across the 8 tb groups (overlay on s_buf) ----
    float* s_red = s_buf;
#pragma unroll
    for (int ci = 0; ci < 4; ci++)
#pragma unroll
        for (int sl = 0; sl < 4; sl++)
            s_red[(tb * 32 + tc) * 16 + ci * 4 + sl] = acc[ci][sl];
    __syncthreads();

    for (int rr = tid; rr < 512; rr += 256) {
        int tcq = rr >> 4, ci = (rr >> 2) & 3, sl = rr & 3;
        float s = 0.f;
#pragma unroll
        for (int g = 0; g < 8; g++)
            s += s_red[(g * 32 + tcq) * 16 + ci * 4 + sl];
        int c = tcq * 4 + ci;
        int ft = c >> 5, f = c & 31;
        int col = -1;
        if (ft == 0)      { if (sl == 0) col = 0; }        // out_0x0_0
        else if (ft == 1) { if (sl < 3)  col = 1 + sl; }   // out_0x1_1
        else if (ft == 2) { if (sl < 3)  col = 4 + sl; }   // out_1x0_1
        else              {              col = 7 + sl; }   // out_1x1_0/1
        if (col >= 0) s_cat[f][col] = s;
    }
    __syncthreads();

    // ---- self-interaction + equivariant activation ----
    if (tid < 32) {
        const int g = tid;
        const float* w0p = w_si0 + g * (2 * FF);
        const float* w1p = w_si1 + g * (3 * FF);
        float si0 = 0.f, sx = 0.f, sy = 0.f, sz = 0.f;
#pragma unroll 8
        for (int f2 = 0; f2 < 32; f2++) {
            const float* c = s_cat[f2];
            si0 += w0p[f2] * c[0] + w0p[32 + f2] * c[7];
            const float wa = w1p[f2], wb = w1p[32 + f2], wc = w1p[64 + f2];
            sx += wa * c[1] + wb * c[4] + wc * c[8];
            sy += wa * c[2] + wb * c[5] + wc * c[9];
            sz += wa * c[3] + wb * c[6] + wc * c[10];
        }
        const float o0v = sspf(si0 + b_act0[g]);
        const float nn  = sx * sx + sy * sy + sz * sz;
        const float n1  = sqrtf(fmaxf(nn, 1e-7f));
        const float a1v = sspf(n1 + b_act1[g]);
        const float sc  = a1v / n1;

        out[(size_t)ma * SI + g] = o0v;                      // o0: (M,A,SI,1)
        float* o1 = out + (size_t)MM * AA * SI + ((size_t)ma * SI + g) * 3;
        o1[0] = sx * sc;
        o1[1] = sy * sc;
        o1[2] = sz * sc;
    }
}

// ---------------------------------------------------------------------------
extern "C" void kernel_launch(void* const* d_in, const int* in_sizes, int n_in,
                              void* d_out, int out_size)
{
    (void)in_sizes; (void)n_in; (void)out_size;

    const float* image   = (const float*)d_in[0];
    const float* vectors = (const float*)d_in[1];
    const float* feat0   = (const float*)d_in[2];
    const float* feat1   = (const float*)d_in[3];

    Wptrs wp;
    for (int filt = 0; filt < 4; filt++) {
        wp.w1[filt] = (const float*)d_in[4 + filt * 4 + 0];
        wp.b1[filt] = (const float*)d_in[4 + filt * 4 + 1];
        wp.w2[filt] = (const float*)d_in[4 + filt * 4 + 2];
        wp.b2[filt] = (const float*)d_in[4 + filt * 4 + 3];
    }
    const float* w_si0  = (const float*)d_in[20];
    const float* w_si1  = (const float*)d_in[21];
    const float* b_act0 = (const float*)d_in[22];
    const float* b_act1 = (const float*)d_in[23];

    prep_kernel<<<32, 256>>>(wp);
    conv_kernel<<<MM * AA, 256>>>(image, vectors, feat0, feat1,
                                  w_si0, w_si1, b_act0, b_act1,
                                  (float*)d_out);
}

// round 8
// speedup vs baseline: 1.0009x; 1.0009x over previous
#include <cuda_runtime.h>
#include <cstddef>

// Problem constants (fixed by the dataset instance)
#define MM   4
#define AA   256
#define RBF  64
#define FF   32
#define HH   32
#define SI   32
#define CC   128   // 4 filters * FF radial columns

// Precombined radial weights, row-major over k: g_Wt[k*CC + c]
__device__ float g_Wt[RBF * CC];
__device__ float g_bias[CC];

struct Wptrs {
    const float* w1[4];
    const float* b1[4];
    const float* w2[4];
    const float* b2[4];
};

// ---------------------------------------------------------------------------
// Precompute W = w1 @ w2 (per filter), bias = b1 @ w2 + b2.
// g_Wt[k][c], c = filt*32 + f  (filt order: 00, 01, 10, 11).
// ---------------------------------------------------------------------------
__global__ void prep_kernel(Wptrs wp) {
    int idx = blockIdx.x * blockDim.x + threadIdx.x;
    if (idx < CC * RBF) {
        int c = idx & (CC - 1);
        int k = idx >> 7;
        int filt = c >> 5;
        int f = c & 31;
        const float* w1 = wp.w1[filt];
        const float* w2 = wp.w2[filt];
        float s = 0.f;
#pragma unroll
        for (int h = 0; h < HH; h++)
            s += w1[k * HH + h] * w2[h * FF + f];
        g_Wt[k * CC + c] = s;
        if (k == 0) {
            float bs = wp.b2[filt][f];
            const float* b1 = wp.b1[filt];
#pragma unroll
            for (int h = 0; h < HH; h++)
                bs += b1[h] * w2[h * FF + f];
            g_bias[c] = bs;
        }
    }
}

// ---------------------------------------------------------------------------
// Packed fp32x2 helpers (Blackwell FFMA2 — PTX-only path)
// ---------------------------------------------------------------------------
typedef unsigned long long u64;

__device__ __forceinline__ u64 ffma2(u64 a, u64 b, u64 c) {
    u64 d;
    asm("fma.rn.f32x2 %0, %1, %2, %3;" : "=l"(d) : "l"(a), "l"(b), "l"(c));
    return d;
}
__device__ __forceinline__ u64 splat2(float x) {
    u64 d;
    asm("mov.b64 %0, {%1, %1};" : "=l"(d) : "f"(x));
    return d;
}
__device__ __forceinline__ float2 unpk(u64 a) {
    float2 r;
    asm("mov.b64 {%0, %1}, %2;" : "=f"(r.x), "=f"(r.y) : "l"(a));
    return r;
}
__device__ __forceinline__ float sspf(float x) {
    return logf(0.5f * expf(x) + 0.5f);   // shifted softplus
}

// ---------------------------------------------------------------------------
// Main fused kernel: one block per (m, a).  256 threads.
//   tc = tid>>3 (0..31): 4 radial columns c = 4*tc..4*tc+3 (one filter/warp)
//   tb = tid&7  (0..7) : 8 neighbor rows per 64-row chunk
// Radial GEMM is register-tiled 8b x 4c with packed f32x2 accumulators;
// image chunk lives transposed in smem (Ism[k][b]); W streamed via LDG.128.
// ---------------------------------------------------------------------------
__global__ void __launch_bounds__(256, 2) conv_kernel(
    const float* __restrict__ image,
    const float* __restrict__ vectors,
    const float* __restrict__ feat0,
    const float* __restrict__ feat1,
    const float* __restrict__ w_si0,
    const float* __restrict__ w_si1,
    const float* __restrict__ b_act0,
    const float* __restrict__ b_act1,
    float* __restrict__ out)
{
    const int ma  = blockIdx.x;        // m*AA + a
    const int m   = ma >> 8;
    const int tid = threadIdx.x;
    const int tc  = tid >> 3;          // 0..31 column group
    const int tb  = tid & 7;           // 0..7  b group
    const int filt  = tc >> 3;         // 0..3 (uniform within warp)
    const int fbase = (tc & 7) * 4;    // f of ci=0

    __shared__ __align__(16) float s_buf[RBF * 64];  // Ism[k][b]; later s_red
    __shared__ float s_v[64][4];
    __shared__ float s_cat[FF][12];

    float (*Ism)[64] = (float (*)[64])s_buf;

    const float* imgbase = image   + (size_t)ma * (AA * RBF);
    const float* vbase   = vectors + (size_t)ma * (AA * 3);
    const float* f0base  = feat0   + (size_t)m  * (AA * FF);
    const float* f1base  = feat1   + (size_t)m  * (AA * FF * 3);

    float bias[4];
    {
        float4 bb = *(const float4*)(g_bias + tc * 4);
        bias[0] = bb.x; bias[1] = bb.y; bias[2] = bb.z; bias[3] = bb.w;
    }

    float acc[4][4];
#pragma unroll
    for (int ci = 0; ci < 4; ci++)
#pragma unroll
        for (int sl = 0; sl < 4; sl++) acc[ci][sl] = 0.f;

    // ---- register-staged image/vector chunk staging ----
    const int sb  = tid & 63;          // b row within chunk
    const int skq = tid >> 6;          // which 16-k slice
    float4 sI[4];
    float  sv = 0.f;

    auto loadregs = [&](int chunk) {
        const float4* src = (const float4*)(imgbase +
            (size_t)(chunk * 64 + sb) * RBF + skq * 16);
#pragma unroll
        for (int j = 0; j < 4; j++) sI[j] = src[j];
        if (tid < 192) sv = vbase[chunk * 192 + tid];
    };
    auto stsregs = [&]() {
#pragma unroll
        for (int j = 0; j < 4; j++) {
            const int k0 = skq * 16 + j * 4;
            Ism[k0 + 0][sb] = sI[j].x;
            Ism[k0 + 1][sb] = sI[j].y;
            Ism[k0 + 2][sb] = sI[j].z;
            Ism[k0 + 3][sb] = sI[j].w;
        }
        if (tid < 192) s_v[tid / 3][tid % 3] = sv;
    };

    loadregs(0);
    stsregs();
    __syncthreads();

    const float* wbase = g_Wt + tc * 4;

    for (int chunk = 0; chunk < 4; chunk++) {
        if (chunk < 3) loadregs(chunk + 1);   // prefetch next chunk into regs

        // ---- 8b x 4c register-tiled GEMM over k=64 ----
        u64 t[4][4];
#pragma unroll
        for (int ci = 0; ci < 4; ci++)
#pragma unroll
            for (int bp = 0; bp < 4; bp++) t[ci][bp] = 0ULL;

#pragma unroll 8
        for (int k = 0; k < 64; k++) {
            float4 w4 = *(const float4*)(wbase + k * CC);       // LDG.128 (L1)
            const u64* ip = (const u64*)&Ism[k][tb * 8];        // 2x LDS.128
            u64 i0 = ip[0], i1 = ip[1], i2 = ip[2], i3 = ip[3];
            u64 w0 = splat2(w4.x), w1 = splat2(w4.y);
            u64 w2 = splat2(w4.z), w3 = splat2(w4.w);
            t[0][0] = ffma2(i0, w0, t[0][0]); t[0][1] = ffma2(i1, w0, t[0][1]);
            t[0][2] = ffma2(i2, w0, t[0][2]); t[0][3] = ffma2(i3, w0, t[0][3]);
            t[1][0] = ffma2(i0, w1, t[1][0]); t[1][1] = ffma2(i1, w1, t[1][1]);
            t[1][2] = ffma2(i2, w1, t[1][2]); t[1][3] = ffma2(i3, w1, t[1][3]);
            t[2][0] = ffma2(i0, w2, t[2][0]); t[2][1] = ffma2(i1, w2, t[2][1]);
            t[2][2] = ffma2(i2, w2, t[2][2]); t[2][3] = ffma2(i3, w2, t[2][3]);
            t[3][0] = ffma2(i0, w3, t[3][0]); t[3][1] = ffma2(i1, w3, t[3][1]);
            t[3][2] = ffma2(i2, w3, t[3][2]); t[3][3] = ffma2(i3, w3, t[3][3]);
        }

        // ---- immediate contraction over this chunk's 8 b rows ----
#pragma unroll
        for (int bp = 0; bp < 4; bp++) {
            float r[2][4];
#pragma unroll
            for (int ci = 0; ci < 4; ci++) {
                float2 u = unpk(t[ci][bp]);
                r[0][ci] = u.x + bias[ci];
                r[1][ci] = u.y + bias[ci];
            }
#pragma unroll
            for (int h = 0; h < 2; h++) {
                const int bl = tb * 8 + bp * 2 + h;
                const int b  = chunk * 64 + bl;

                if (filt == 0) {
                    // out_0x0_0: acc0 += r * feat0
                    float4 p = *(const float4*)(f0base + b * FF + fbase);
                    acc[0][0] += r[h][0] * p.x;
                    acc[1][0] += r[h][1] * p.y;
                    acc[2][0] += r[h][2] * p.z;
                    acc[3][0] += r[h][3] * p.w;
                } else if (filt == 1) {
                    // out_0x1_1: acc[0..2] += (r*mask)*feat0 * v
                    float vx = s_v[bl][0], vy = s_v[bl][1], vz = s_v[bl][2];
                    float n2 = vx * vx + vy * vy + vz * vz;
                    float mk = (n2 < 1e-14f) ? 0.f : 1.f;
                    float4 p = *(const float4*)(f0base + b * FF + fbase);
                    float pp[4] = {p.x, p.y, p.z, p.w};
#pragma unroll
                    for (int ci = 0; ci < 4; ci++) {
                        float tp = r[h][ci] * mk * pp[ci];
                        acc[ci][0] += tp * vx;
                        acc[ci][1] += tp * vy;
                        acc[ci][2] += tp * vz;
                    }
                } else if (filt == 2) {
                    // out_1x0_1: acc[0..2] += r * feat1
                    const float4* qp = (const float4*)(f1base +
                        (size_t)(b * FF + fbase) * 3);
                    float4 qa = qp[0], qb = qp[1], qc = qp[2];
                    float q[12] = {qa.x, qa.y, qa.z, qa.w,
                                   qb.x, qb.y, qb.z, qb.w,
                                   qc.x, qc.y, qc.z, qc.w};
#pragma unroll
                    for (int ci = 0; ci < 4; ci++) {
                        acc[ci][0] += r[h][ci] * q[ci * 3 + 0];
                        acc[ci][1] += r[h][ci] * q[ci * 3 + 1];
                        acc[ci][2] += r[h][ci] * q[ci * 3 + 2];
                    }
                } else {
                    // out_1x1_0 (v.q) + out_1x1_1 (v x q)
                    float vx = s_v[bl][0], vy = s_v[bl][1], vz = s_v[bl][2];
                    float n2 = vx * vx + vy * vy + vz * vz;
                    float mk = (n2 < 1e-14f) ? 0.f : 1.f;
                    const float4* qp = (const float4*)(f1base +
                        (size_t)(b * FF + fbase) * 3);
                    float4 qa = qp[0], qb = qp[1], qc = qp[2];
                    float q[12] = {qa.x, qa.y, qa.z, qa.w,
                                   qb.x, qb.y, qb.z, qb.w,
                                   qc.x, qc.y, qc.z, qc.w};
#pragma unroll
                    for (int ci = 0; ci < 4; ci++) {
                        float rm = r[h][ci] * mk;
                        float q0 = q[ci * 3], q1 = q[ci * 3 + 1], q2 = q[ci * 3 + 2];
                        acc[ci][0] += rm * (vx * q0 + vy * q1 + vz * q2);
                        acc[ci][1] += rm * (vy * q2 - vz * q1);
                        acc[ci][2] += rm * (vz * q0 - vx * q2);
                        acc[ci][3] += rm * (vx * q1 - vy * q0);
                    }
                }
            }
        }

        __syncthreads();                 // everyone done reading Ism / s_v
        if (chunk < 3) {
            stsregs();                   // write next chunk
            __syncthreads();
        }
    }

    // ---- reduce across the 8 tb groups (overlay on s_buf) ----
    float* s_red = s_buf;
#pragma unroll
    for (int ci = 0; ci < 4; ci++)
#pragma unroll
        for (int sl = 0; sl < 4; sl++)
            s_red[(tb * 32 + tc) * 16 + ci * 4 + sl] = acc[ci][sl];
    __syncthreads();

    for (int rr = tid; rr < 512; rr += 256) {
        int tcq = rr >> 4, ci = (rr >> 2) & 3, sl = rr & 3;
        float s = 0.f;
#pragma unroll
        for (int g = 0; g < 8; g++)
            s += s_red[(g * 32 + tcq) * 16 + ci * 4 + sl];
        int c = tcq * 4 + ci;
        int ft = c >> 5, f = c & 31;
        int col = -1;
        if (ft == 0)      { if (sl == 0) col = 0; }        // out_0x0_0
        else if (ft == 1) { if (sl < 3)  col = 1 + sl; }   // out_0x1_1
        else if (ft == 2) { if (sl < 3)  col = 4 + sl; }   // out_1x0_1
        else              {              col = 7 + sl; }   // out_1x1_0/1
        if (col >= 0) s_cat[f][col] = s;
    }
    __syncthreads();

    // ---- self-interaction + equivariant activation ----
    if (tid < 32) {
        const int g = tid;
        const float* w0p = w_si0 + g * (2 * FF);
        const float* w1p = w_si1 + g * (3 * FF);
        float si0 = 0.f, sx = 0.f, sy = 0.f, sz = 0.f;
#pragma unroll 8
        for (int f2 = 0; f2 < 32; f2++) {
            const float* c = s_cat[f2];
            si0 += w0p[f2] * c[0] + w0p[32 + f2] * c[7];
            const float wa = w1p[f2], wb = w1p[32 + f2], wc = w1p[64 + f2];
            sx += wa * c[1] + wb * c[4] + wc * c[8];
            sy += wa * c[2] + wb * c[5] + wc * c[9];
            sz += wa * c[3] + wb * c[6] + wc * c[10];
        }
        const float o0v = sspf(si0 + b_act0[g]);
        const float nn  = sx * sx + sy * sy + sz * sz;
        const float n1  = sqrtf(fmaxf(nn, 1e-7f));
        const float a1v = sspf(n1 + b_act1[g]);
        const float sc  = a1v / n1;

        out[(size_t)ma * SI + g] = o0v;                      // o0: (M,A,SI,1)
        float* o1 = out + (size_t)MM * AA * SI + ((size_t)ma * SI + g) * 3;
        o1[0] = sx * sc;
        o1[1] = sy * sc;
        o1[2] = sz * sc;
    }
}

// ---------------------------------------------------------------------------
extern "C" void kernel_launch(void* const* d_in, const int* in_sizes, int n_in,
                              void* d_out, int out_size)
{
    (void)in_sizes; (void)n_in; (void)out_size;

    const float* image   = (const float*)d_in[0];
    const float* vectors = (const float*)d_in[1];
    const float* feat0   = (const float*)d_in[2];
    const float* feat1   = (const float*)d_in[3];

    Wptrs wp;
    for (int filt = 0; filt < 4; filt++) {
        wp.w1[filt] = (const float*)d_in[4 + filt * 4 + 0];
        wp.b1[filt] = (const float*)d_in[4 + filt * 4 + 1];
        wp.w2[filt] = (const float*)d_in[4 + filt * 4 + 2];
        wp.b2[filt] = (const float*)d_in[4 + filt * 4 + 3];
    }
    const float* w_si0  = (const float*)d_in[20];
    const float* w_si1  = (const float*)d_in[21];
    const float* b_act0 = (const float*)d_in[22];
    const float* b_act1 = (const float*)d_in[23];

    prep_kernel<<<32, 256>>>(wp);
    conv_kernel<<<MM * AA, 256>>>(image, vectors, feat0, feat1,
                                  w_si0, w_si1, b_act0, b_act1,
                                  (float*)d_out);
}